// round 1
// baseline (speedup 1.0000x reference)
#include <cuda_runtime.h>

// ---------------- device scratch (no allocations allowed) ----------------
#define NMAX 4096
__device__ float g_scores[NMAX];
__device__ float g_pm[NMAX * 3];   // xyz / RADIUS
__device__ float g_pc[NMAX * 3];   // xyz / (sqrt(2)*RADIUS)
__device__ float g_uv[NMAX * 6];   // tangent u,v
__device__ float g_h1[NMAX * 16];  // pre-groupnorm h
__device__ float g_h[NMAX * 16];   // groupnormed h
__device__ float g_nuv[NMAX * 9];  // [n, t1, t2]
__device__ float g_y[NMAX * 16];   // conv output
__device__ float g_y2[NMAX * 16];  // after no_w MLP
__device__ float g_yn[NMAX * 16];  // after gn_out

__device__ __forceinline__ float lk(float x) { return x >= 0.f ? x : 0.2f * x; }

__device__ __forceinline__ unsigned long long pk2(float a, float b) {
    unsigned long long r;
    asm("mov.b64 %0, {%1, %2};" : "=l"(r) : "f"(a), "f"(b));
    return r;
}
__device__ __forceinline__ unsigned long long ffma2(unsigned long long a,
                                                    unsigned long long b,
                                                    unsigned long long c) {
    unsigned long long d;
    asm("fma.rn.f32x2 %0, %1, %2, %3;" : "=l"(d) : "l"(a), "l"(b), "l"(c));
    return d;
}
__device__ __forceinline__ float2 unpk(unsigned long long v) {
    float2 f;
    asm("mov.b64 {%0, %1}, %2;" : "=f"(f.x), "=f"(f.y) : "l"(v));
    return f;
}

// ---------------- Kernel A: per-point preprocessing ----------------
__global__ void kA(const float* __restrict__ xyz, const float* __restrict__ nrm,
                   const float* __restrict__ feats,
                   const float* __restrict__ osw1, const float* __restrict__ osb1,
                   const float* __restrict__ osw2, const float* __restrict__ osb2,
                   const float* __restrict__ niw1, const float* __restrict__ nib1,
                   const float* __restrict__ niw2, const float* __restrict__ nib2,
                   int N) {
    __shared__ float sOs1[256], sNi1[256], sNi2[256];
    __shared__ float sOsb1[16], sOsw2[16], sNib1[16], sNib2[16];
    int t = threadIdx.x;
    if (t < 256) { sOs1[t] = osw1[t]; sNi1[t] = niw1[t]; sNi2[t] = niw2[t]; }
    if (t < 16)  { sOsb1[t] = osb1[t]; sOsw2[t] = osw2[t]; sNib1[t] = nib1[t]; sNib2[t] = nib2[t]; }
    __syncthreads();
    int i = blockIdx.x * 256 + t;
    if (i >= N) return;

    float f[16];
#pragma unroll
    for (int k = 0; k < 16; k++) f[k] = feats[i * 16 + k];

    // scores = leaky(f@os_w1.T + b1) @ os_w2.T + b2
    float sc = osb2[0];
#pragma unroll
    for (int u = 0; u < 16; u++) {
        float a = sOsb1[u];
#pragma unroll
        for (int k = 0; k < 16; k++) a = fmaf(f[k], sOs1[u * 16 + k], a);
        sc = fmaf(lk(a), sOsw2[u], sc);
    }
    g_scores[i] = sc;

    float px = xyz[i * 3 + 0], py = xyz[i * 3 + 1], pz = xyz[i * 3 + 2];
    const float invR = 1.f / 9.f;
    const float invRc = 1.f / (9.f * 1.4142135623730951f);
    g_pm[i * 3 + 0] = px * invR;  g_pm[i * 3 + 1] = py * invR;  g_pm[i * 3 + 2] = pz * invR;
    g_pc[i * 3 + 0] = px * invRc; g_pc[i * 3 + 1] = py * invRc; g_pc[i * 3 + 2] = pz * invRc;

    // tangent vectors
    float nx = nrm[i * 3 + 0], ny = nrm[i * 3 + 1], nz = nrm[i * 3 + 2];
    float s = nz >= 0.f ? 1.f : -1.f;
    float a = -1.f / (s + nz);
    float b = nx * ny * a;
    g_uv[i * 6 + 0] = 1.f + s * nx * nx * a;
    g_uv[i * 6 + 1] = s * b;
    g_uv[i * 6 + 2] = -s * nx;
    g_uv[i * 6 + 3] = b;
    g_uv[i * 6 + 4] = s + ny * ny * a;
    g_uv[i * 6 + 5] = -ny;

    // h1 = leaky(leaky(f@ni_w1.T+b1)@ni_w2.T+b2)
    float h0[16];
#pragma unroll
    for (int u = 0; u < 16; u++) {
        float acc = sNib1[u];
#pragma unroll
        for (int k = 0; k < 16; k++) acc = fmaf(f[k], sNi1[u * 16 + k], acc);
        h0[u] = lk(acc);
    }
#pragma unroll
    for (int v = 0; v < 16; v++) {
        float acc = sNib2[v];
#pragma unroll
        for (int k = 0; k < 16; k++) acc = fmaf(h0[k], sNi2[v * 16 + k], acc);
        g_h1[i * 16 + v] = lk(acc);
    }
}

// ---------------- GroupNorm (GROUPS=4 over channel-groups x all N), single CTA ----------------
__device__ void gn_body(const float* __restrict__ xin, const float* __restrict__ gamma,
                        const float* __restrict__ beta, float* __restrict__ xout, int N) {
    __shared__ float red[32][8];
    __shared__ float fin[8];
    __shared__ float smean[4], sinv[4];
    int t = threadIdx.x;
    float s0 = 0, s1 = 0, s2 = 0, s3 = 0, q0 = 0, q1 = 0, q2 = 0, q3 = 0;
    for (int n = t; n < N; n += blockDim.x) {
        const float4* r = reinterpret_cast<const float4*>(xin + n * 16);
        float4 v0 = r[0], v1 = r[1], v2 = r[2], v3 = r[3];
        s0 += v0.x + v0.y + v0.z + v0.w; q0 += v0.x * v0.x + v0.y * v0.y + v0.z * v0.z + v0.w * v0.w;
        s1 += v1.x + v1.y + v1.z + v1.w; q1 += v1.x * v1.x + v1.y * v1.y + v1.z * v1.z + v1.w * v1.w;
        s2 += v2.x + v2.y + v2.z + v2.w; q2 += v2.x * v2.x + v2.y * v2.y + v2.z * v2.z + v2.w * v2.w;
        s3 += v3.x + v3.y + v3.z + v3.w; q3 += v3.x * v3.x + v3.y * v3.y + v3.z * v3.z + v3.w * v3.w;
    }
#pragma unroll
    for (int off = 16; off > 0; off >>= 1) {
        s0 += __shfl_down_sync(0xffffffffu, s0, off);
        s1 += __shfl_down_sync(0xffffffffu, s1, off);
        s2 += __shfl_down_sync(0xffffffffu, s2, off);
        s3 += __shfl_down_sync(0xffffffffu, s3, off);
        q0 += __shfl_down_sync(0xffffffffu, q0, off);
        q1 += __shfl_down_sync(0xffffffffu, q1, off);
        q2 += __shfl_down_sync(0xffffffffu, q2, off);
        q3 += __shfl_down_sync(0xffffffffu, q3, off);
    }
    int lane = t & 31, w = t >> 5;
    if (lane == 0) {
        red[w][0] = s0; red[w][1] = s1; red[w][2] = s2; red[w][3] = s3;
        red[w][4] = q0; red[w][5] = q1; red[w][6] = q2; red[w][7] = q3;
    }
    __syncthreads();
    if (t < 8) {
        float a = 0;
        int nw = blockDim.x >> 5;
        for (int k = 0; k < nw; k++) a += red[k][t];
        fin[t] = a;
    }
    __syncthreads();
    if (t < 4) {
        float cnt = (float)(4 * N);
        float mn = fin[t] / cnt;
        float vv = fin[t + 4] / cnt - mn * mn;
        smean[t] = mn;
        sinv[t] = rsqrtf(vv + 1e-5f);
    }
    __syncthreads();
    for (int idx = t; idx < N * 16; idx += blockDim.x) {
        int c = idx & 15;
        int gg = c >> 2;
        xout[idx] = (xin[idx] - smean[gg]) * sinv[gg] * gamma[c] + beta[c];
    }
}
__global__ void kGN_in(const float* __restrict__ gamma, const float* __restrict__ beta, int N) {
    gn_body(g_h1, gamma, beta, g_h, N);
}
__global__ void kGN_out(const float* __restrict__ gamma, const float* __restrict__ beta, int N) {
    gn_body(g_y2, gamma, beta, g_yn, N);
}

// ---------------- Kernel C: load_mesh N^2 (nuv construction) ----------------
__global__ void kMesh(const float* __restrict__ nrm, int N) {
    // block: 128 threads, 16 i's x 8 j-slices
    __shared__ float sred[8][16][2];
    int t = threadIdx.x;
    int il = t & 15, slice = t >> 4;
    int i = blockIdx.x * 16 + il;
    if (i >= N) return;

    float pix = g_pm[i * 3 + 0], piy = g_pm[i * 3 + 1], piz = g_pm[i * 3 + 2];
    float nix = nrm[i * 3 + 0], niy = nrm[i * 3 + 1], niz = nrm[i * 3 + 2];
    float ux = g_uv[i * 6 + 0], uy = g_uv[i * 6 + 1], uz = g_uv[i * 6 + 2];
    float vx = g_uv[i * 6 + 3], vy = g_uv[i * 6 + 4], vz = g_uv[i * 6 + 5];

    float ov0 = 0.f, ov1 = 0.f;
    int per = N >> 3;
    int j0 = slice * per;
    for (int j = j0; j < j0 + per; j++) {
        float dx = g_pm[j * 3 + 0] - pix;
        float dy = g_pm[j * 3 + 1] - piy;
        float dz = g_pm[j * 3 + 2] - piz;
        float d2 = dx * dx + dy * dy + dz * dz;
        float cs = nrm[j * 3 + 0] * nix + nrm[j * 3 + 1] * niy + nrm[j * 3 + 2] * niz;
        float tt = 2.f - cs;
        float wj = __expf(-d2 * tt * tt) * g_scores[j];
        ov0 = fmaf(wj, ux * dx + uy * dy + uz * dz, ov0);
        ov1 = fmaf(wj, vx * dx + vy * dy + vz * dz, ov1);
    }
    sred[slice][il][0] = ov0;
    sred[slice][il][1] = ov1;
    __syncthreads();
    if (slice == 0) {
#pragma unroll
        for (int k = 1; k < 8; k++) { ov0 += sred[k][il][0]; ov1 += sred[k][il][1]; }
        ov0 += 1e-5f; ov1 += 1e-5f;
        float nr = fmaxf(sqrtf(ov0 * ov0 + ov1 * ov1), 1e-12f);
        float ex = ov0 / nr, ey = ov1 / nr;
        g_nuv[i * 9 + 0] = nix; g_nuv[i * 9 + 1] = niy; g_nuv[i * 9 + 2] = niz;
        g_nuv[i * 9 + 3] = ex * ux + ey * vx;
        g_nuv[i * 9 + 4] = ex * uy + ey * vy;
        g_nuv[i * 9 + 5] = ex * uz + ey * vz;
        g_nuv[i * 9 + 6] = -ey * ux + ex * vx;
        g_nuv[i * 9 + 7] = -ey * uy + ex * vy;
        g_nuv[i * 9 + 8] = -ey * uz + ex * vz;
    }
}

// ---------------- Kernel D: main conv N^2 (packed f32x2 path) ----------------
#define TI 8
#define TJ 32
#define GJS (TJ + 1)  // padded jj stride (ull units)

#define DO_HP(hp, hx, hy) do {                                  \
    unsigned long long m = B2[hp];                              \
    m = ffma2(A2[hp][0], g0, m);                                \
    m = ffma2(A2[hp][1], g1, m);                                \
    m = ffma2(A2[hp][2], g2, m);                                \
    m = ffma2(A2[hp][3], g3, m);                                \
    m = ffma2(A2[hp][4], g4, m);                                \
    m = ffma2(A2[hp][5], g5, m);                                \
    m = ffma2(A2[hp][6], g6, m);                                \
    m = ffma2(A2[hp][7], g7, m);                                \
    float2 mf = unpk(m);                                        \
    sx = fmaf(fmaxf(mf.x, 0.f), (hx), sx);                      \
    sy = fmaf(fmaxf(mf.y, 0.f), (hy), sy);                      \
} while (0)

__global__ void __launch_bounds__(128, 2)
kConv(const float* __restrict__ nrm, const float* __restrict__ cva1,
      const float* __restrict__ cvb1, const float* __restrict__ cva2,
      const float* __restrict__ cvb2, int N) {
    // layout [ii][c][jj] (padded) : conflict-free stores and broadcast loads
    __shared__ __align__(16) unsigned long long sm_g[TI * 8 * GJS];
    __shared__ float4 sm_h[TJ][4];
    __shared__ float sm_w[TI][TJ + 1];
    __shared__ float sm_pi[TI][4];
    __shared__ float sm_nv[TI][9];
    __shared__ float sm_a1[24];
    __shared__ float sm_b1[8];

    int t = threadIdx.x;
    int o = t & 15, ii4 = t >> 4;
    int ibase = blockIdx.x * TI;

    // preload per-o packed weights into registers
    unsigned long long A2[8][8], B2[8];
#pragma unroll
    for (int hp = 0; hp < 8; hp++) {
        int r0 = (o * 16 + 2 * hp) * 8;
#pragma unroll
        for (int c = 0; c < 8; c++) A2[hp][c] = pk2(cva2[r0 + c], cva2[r0 + 8 + c]);
        B2[hp] = pk2(cvb2[o * 16 + 2 * hp], cvb2[o * 16 + 2 * hp + 1]);
    }
    if (t < TI) {
        int i = ibase + t;
        sm_pi[t][0] = g_pc[i * 3 + 0];
        sm_pi[t][1] = g_pc[i * 3 + 1];
        sm_pi[t][2] = g_pc[i * 3 + 2];
#pragma unroll
        for (int k = 0; k < 9; k++) sm_nv[t][k] = g_nuv[i * 9 + k];
    }
    if (t >= 32 && t < 56) sm_a1[t - 32] = cva1[t - 32];
    if (t >= 64 && t < 72) sm_b1[t - 64] = cvb1[t - 64];
    __syncthreads();

    float acc = 0.f;
    for (int jt = 0; jt < N; jt += TJ) {
        // ---- phase 1: window + packed g for 8 x 32 pairs ----
        {
            int pjj = t & 31;
            int j = jt + pjj;
            float pjx = g_pc[j * 3 + 0], pjy = g_pc[j * 3 + 1], pjz = g_pc[j * 3 + 2];
            float njx = nrm[j * 3 + 0], njy = nrm[j * 3 + 1], njz = nrm[j * 3 + 2];
#pragma unroll
            for (int rep = 0; rep < 2; rep++) {
                int pii = (t >> 5) + rep * 4;
                float dx = pjx - sm_pi[pii][0];
                float dy = pjy - sm_pi[pii][1];
                float dz = pjz - sm_pi[pii][2];
                float d2 = dx * dx + dy * dy + dz * dz;
                float cs = njx * sm_nv[pii][0] + njy * sm_nv[pii][1] + njz * sm_nv[pii][2];
                float tt = 2.f - cs;
                float w = __expf(-d2 * tt * tt);
                float X0 = dx * sm_nv[pii][0] + dy * sm_nv[pii][1] + dz * sm_nv[pii][2];
                float X1 = dx * sm_nv[pii][3] + dy * sm_nv[pii][4] + dz * sm_nv[pii][5];
                float X2 = dx * sm_nv[pii][6] + dy * sm_nv[pii][7] + dz * sm_nv[pii][8];
                sm_w[pii][pjj] = w;
#pragma unroll
                for (int c = 0; c < 8; c++) {
                    float gv = fmaf(X0, sm_a1[c * 3 + 0],
                               fmaf(X1, sm_a1[c * 3 + 1],
                               fmaf(X2, sm_a1[c * 3 + 2], sm_b1[c])));
                    gv = fmaxf(gv, 0.f);
                    sm_g[(pii * 8 + c) * GJS + pjj] = pk2(gv, gv);
                }
            }
        }
        // ---- h tile (128 threads = 32 rows x 4 float4) ----
        {
            int hjj = t >> 2, hq = t & 3;
            sm_h[hjj][hq] = reinterpret_cast<const float4*>(g_h + (jt + hjj) * 16)[hq];
        }
        __syncthreads();

        // ---- phase 2: packed inner product ----
        const unsigned long long* gb = &sm_g[ii4 * 8 * GJS];
#pragma unroll 2
        for (int jj = 0; jj < TJ; jj++) {
            unsigned long long g0 = gb[0 * GJS + jj];
            unsigned long long g1 = gb[1 * GJS + jj];
            unsigned long long g2 = gb[2 * GJS + jj];
            unsigned long long g3 = gb[3 * GJS + jj];
            unsigned long long g4 = gb[4 * GJS + jj];
            unsigned long long g5 = gb[5 * GJS + jj];
            unsigned long long g6 = gb[6 * GJS + jj];
            unsigned long long g7 = gb[7 * GJS + jj];
            float4 hA = sm_h[jj][0];
            float4 hB = sm_h[jj][1];
            float4 hC = sm_h[jj][2];
            float4 hD = sm_h[jj][3];
            float w = sm_w[ii4][jj];
            float sx = 0.f, sy = 0.f;
            DO_HP(0, hA.x, hA.y);
            DO_HP(1, hA.z, hA.w);
            DO_HP(2, hB.x, hB.y);
            DO_HP(3, hB.z, hB.w);
            DO_HP(4, hC.x, hC.y);
            DO_HP(5, hC.z, hC.w);
            DO_HP(6, hD.x, hD.y);
            DO_HP(7, hD.z, hD.w);
            acc = fmaf(w, sx + sy, acc);
        }
        __syncthreads();
    }
    g_y[(ibase + ii4) * 16 + o] = acc;
}

// ---------------- Kernel E1: y -> y2 (no_w MLP with leaky) ----------------
__global__ void kE1(const float* __restrict__ w1, const float* __restrict__ b1,
                    const float* __restrict__ w2, const float* __restrict__ b2, int N) {
    __shared__ float s1[256], s2[256], sb1[16], sb2[16];
    int t = threadIdx.x;
    if (t < 256) { s1[t] = w1[t]; s2[t] = w2[t]; }
    if (t < 16)  { sb1[t] = b1[t]; sb2[t] = b2[t]; }
    __syncthreads();
    int i = blockIdx.x * 256 + t;
    if (i >= N) return;
    float yv[16], t1[16];
#pragma unroll
    for (int k = 0; k < 16; k++) yv[k] = g_y[i * 16 + k];
#pragma unroll
    for (int u = 0; u < 16; u++) {
        float a = sb1[u];
#pragma unroll
        for (int k = 0; k < 16; k++) a = fmaf(yv[k], s1[u * 16 + k], a);
        t1[u] = lk(a);
    }
#pragma unroll
    for (int v = 0; v < 16; v++) {
        float a = sb2[v];
#pragma unroll
        for (int k = 0; k < 16; k++) a = fmaf(t1[k], s2[v * 16 + k], a);
        g_y2[i * 16 + v] = lk(a);
    }
}

// ---------------- Kernel E3: final heads + skip ----------------
__global__ void kE3(const float* __restrict__ feats,
                    const float* __restrict__ llw1, const float* __restrict__ llb1,
                    const float* __restrict__ llw2, const float* __restrict__ llb2,
                    const float* __restrict__ ltw, const float* __restrict__ ltb,
                    float* __restrict__ out, int N) {
    __shared__ float sW1[256], sW2[256], sWt[256], sB1[16], sB2[16], sBt[16];
    int t = threadIdx.x;
    if (t < 256) { sW1[t] = llw1[t]; sW2[t] = llw2[t]; sWt[t] = ltw[t]; }
    if (t < 16)  { sB1[t] = llb1[t]; sB2[t] = llb2[t]; sBt[t] = ltb[t]; }
    __syncthreads();
    int i = blockIdx.x * 256 + t;
    if (i >= N) return;
    float yn[16], f[16], t1[16];
#pragma unroll
    for (int k = 0; k < 16; k++) yn[k] = g_yn[i * 16 + k];
#pragma unroll
    for (int k = 0; k < 16; k++) f[k] = feats[i * 16 + k];
#pragma unroll
    for (int u = 0; u < 16; u++) {
        float a = sB1[u];
#pragma unroll
        for (int k = 0; k < 16; k++) a = fmaf(yn[k], sW1[u * 16 + k], a);
        t1[u] = fmaxf(a, 0.f);  // relu
    }
#pragma unroll
    for (int v = 0; v < 16; v++) {
        float xi = sB2[v];
#pragma unroll
        for (int k = 0; k < 16; k++) xi = fmaf(t1[k], sW2[v * 16 + k], xi);
        float xl = sBt[v];
#pragma unroll
        for (int k = 0; k < 16; k++) xl = fmaf(f[k], sWt[v * 16 + k], xl);
        out[i * 16 + v] = xl + xi;
    }
}

// ---------------- launch ----------------
extern "C" void kernel_launch(void* const* d_in, const int* in_sizes, int n_in,
                              void* d_out, int out_size) {
    const float* xyz    = (const float*)d_in[0];
    const float* nrm    = (const float*)d_in[1];
    const float* feats  = (const float*)d_in[2];
    const float* osw1   = (const float*)d_in[3];
    const float* osb1   = (const float*)d_in[4];
    const float* osw2   = (const float*)d_in[5];
    const float* osb2   = (const float*)d_in[6];
    const float* niw1   = (const float*)d_in[7];
    const float* nib1   = (const float*)d_in[8];
    const float* niw2   = (const float*)d_in[9];
    const float* nib2   = (const float*)d_in[10];
    const float* gnig   = (const float*)d_in[11];
    const float* gnib   = (const float*)d_in[12];
    const float* cva1   = (const float*)d_in[13];
    const float* cvb1   = (const float*)d_in[14];
    const float* cva2   = (const float*)d_in[15];
    const float* cvb2   = (const float*)d_in[16];
    const float* now1   = (const float*)d_in[17];
    const float* nob1   = (const float*)d_in[18];
    const float* now2   = (const float*)d_in[19];
    const float* nob2   = (const float*)d_in[20];
    const float* gnog   = (const float*)d_in[21];
    const float* gnob   = (const float*)d_in[22];
    const float* llw1   = (const float*)d_in[23];
    const float* llb1   = (const float*)d_in[24];
    const float* llw2   = (const float*)d_in[25];
    const float* llb2   = (const float*)d_in[26];
    const float* ltw    = (const float*)d_in[27];
    const float* ltb    = (const float*)d_in[28];
    float* out = (float*)d_out;

    int N = in_sizes[0] / 3;  // 4096

    kA<<<(N + 255) / 256, 256>>>(xyz, nrm, feats, osw1, osb1, osw2, osb2,
                                 niw1, nib1, niw2, nib2, N);
    kGN_in<<<1, 1024>>>(gnig, gnib, N);
    kMesh<<<N / 16, 128>>>(nrm, N);
    kConv<<<N / TI, 128>>>(nrm, cva1, cvb1, cva2, cvb2, N);
    kE1<<<(N + 255) / 256, 256>>>(now1, nob1, now2, nob2, N);
    kGN_out<<<1, 1024>>>(gnog, gnob, N);
    kE3<<<(N + 255) / 256, 256>>>(feats, llw1, llb1, llw2, llb2, ltw, ltb, out, N);
}

// round 2
// speedup vs baseline: 1.1696x; 1.1696x over previous
#include <cuda_runtime.h>

// ---------------- device scratch (no allocations allowed) ----------------
#define NMAX 4096
__device__ float g_scores[NMAX];
__device__ float g_pm[NMAX * 3];   // xyz / RADIUS
__device__ float g_pc[NMAX * 3];   // xyz / (sqrt(2)*RADIUS)
__device__ float g_uv[NMAX * 6];   // tangent u,v
__device__ float g_h1[NMAX * 16];  // pre-groupnorm h
__device__ float g_h[NMAX * 16];   // groupnormed h
__device__ float g_nuv[NMAX * 9];  // [n, t1, t2]
__device__ float g_y[NMAX * 16];   // conv output
__device__ float g_y2[NMAX * 16];  // after no_w MLP
__device__ float g_yn[NMAX * 16];  // after gn_out

__device__ __forceinline__ float lk(float x) { return x >= 0.f ? x : 0.2f * x; }

__device__ __forceinline__ unsigned long long pk2(float a, float b) {
    unsigned long long r;
    asm("mov.b64 %0, {%1, %2};" : "=l"(r) : "f"(a), "f"(b));
    return r;
}
__device__ __forceinline__ unsigned long long ffma2(unsigned long long a,
                                                    unsigned long long b,
                                                    unsigned long long c) {
    unsigned long long d;
    asm("fma.rn.f32x2 %0, %1, %2, %3;" : "=l"(d) : "l"(a), "l"(b), "l"(c));
    return d;
}
__device__ __forceinline__ float2 unpk(unsigned long long v) {
    float2 f;
    asm("mov.b64 {%0, %1}, %2;" : "=f"(f.x), "=f"(f.y) : "l"(v));
    return f;
}
// relu on both packed halves via integer max (ALU pipe, not FMA pipe).
// For IEEE floats: x >= 0  <=>  (int)bits >= 0;  max((int)x, 0) == bits(relu(x)).
__device__ __forceinline__ unsigned long long relu2(unsigned long long v) {
    int lo, hi;
    asm("mov.b64 {%0, %1}, %2;" : "=r"(lo), "=r"(hi) : "l"(v));
    lo = lo > 0 ? lo : 0;
    hi = hi > 0 ? hi : 0;
    unsigned long long r;
    asm("mov.b64 %0, {%1, %2};" : "=l"(r) : "r"(lo), "r"(hi));
    return r;
}

// ---------------- Kernel A: per-point preprocessing ----------------
__global__ void kA(const float* __restrict__ xyz, const float* __restrict__ nrm,
                   const float* __restrict__ feats,
                   const float* __restrict__ osw1, const float* __restrict__ osb1,
                   const float* __restrict__ osw2, const float* __restrict__ osb2,
                   const float* __restrict__ niw1, const float* __restrict__ nib1,
                   const float* __restrict__ niw2, const float* __restrict__ nib2,
                   int N) {
    __shared__ float sOs1[256], sNi1[256], sNi2[256];
    __shared__ float sOsb1[16], sOsw2[16], sNib1[16], sNib2[16];
    int t = threadIdx.x;
    if (t < 256) { sOs1[t] = osw1[t]; sNi1[t] = niw1[t]; sNi2[t] = niw2[t]; }
    if (t < 16)  { sOsb1[t] = osb1[t]; sOsw2[t] = osw2[t]; sNib1[t] = nib1[t]; sNib2[t] = nib2[t]; }
    __syncthreads();
    int i = blockIdx.x * 256 + t;
    if (i >= N) return;

    float f[16];
#pragma unroll
    for (int k = 0; k < 16; k++) f[k] = feats[i * 16 + k];

    float sc = osb2[0];
#pragma unroll
    for (int u = 0; u < 16; u++) {
        float a = sOsb1[u];
#pragma unroll
        for (int k = 0; k < 16; k++) a = fmaf(f[k], sOs1[u * 16 + k], a);
        sc = fmaf(lk(a), sOsw2[u], sc);
    }
    g_scores[i] = sc;

    float px = xyz[i * 3 + 0], py = xyz[i * 3 + 1], pz = xyz[i * 3 + 2];
    const float invR = 1.f / 9.f;
    const float invRc = 1.f / (9.f * 1.4142135623730951f);
    g_pm[i * 3 + 0] = px * invR;  g_pm[i * 3 + 1] = py * invR;  g_pm[i * 3 + 2] = pz * invR;
    g_pc[i * 3 + 0] = px * invRc; g_pc[i * 3 + 1] = py * invRc; g_pc[i * 3 + 2] = pz * invRc;

    float nx = nrm[i * 3 + 0], ny = nrm[i * 3 + 1], nz = nrm[i * 3 + 2];
    float s = nz >= 0.f ? 1.f : -1.f;
    float a = -1.f / (s + nz);
    float b = nx * ny * a;
    g_uv[i * 6 + 0] = 1.f + s * nx * nx * a;
    g_uv[i * 6 + 1] = s * b;
    g_uv[i * 6 + 2] = -s * nx;
    g_uv[i * 6 + 3] = b;
    g_uv[i * 6 + 4] = s + ny * ny * a;
    g_uv[i * 6 + 5] = -ny;

    float h0[16];
#pragma unroll
    for (int u = 0; u < 16; u++) {
        float acc = sNib1[u];
#pragma unroll
        for (int k = 0; k < 16; k++) acc = fmaf(f[k], sNi1[u * 16 + k], acc);
        h0[u] = lk(acc);
    }
#pragma unroll
    for (int v = 0; v < 16; v++) {
        float acc = sNib2[v];
#pragma unroll
        for (int k = 0; k < 16; k++) acc = fmaf(h0[k], sNi2[v * 16 + k], acc);
        g_h1[i * 16 + v] = lk(acc);
    }
}

// ---------------- GroupNorm ----------------
__device__ void gn_body(const float* __restrict__ xin, const float* __restrict__ gamma,
                        const float* __restrict__ beta, float* __restrict__ xout, int N) {
    __shared__ float red[32][8];
    __shared__ float fin[8];
    __shared__ float smean[4], sinv[4];
    int t = threadIdx.x;
    float s0 = 0, s1 = 0, s2 = 0, s3 = 0, q0 = 0, q1 = 0, q2 = 0, q3 = 0;
    for (int n = t; n < N; n += blockDim.x) {
        const float4* r = reinterpret_cast<const float4*>(xin + n * 16);
        float4 v0 = r[0], v1 = r[1], v2 = r[2], v3 = r[3];
        s0 += v0.x + v0.y + v0.z + v0.w; q0 += v0.x * v0.x + v0.y * v0.y + v0.z * v0.z + v0.w * v0.w;
        s1 += v1.x + v1.y + v1.z + v1.w; q1 += v1.x * v1.x + v1.y * v1.y + v1.z * v1.z + v1.w * v1.w;
        s2 += v2.x + v2.y + v2.z + v2.w; q2 += v2.x * v2.x + v2.y * v2.y + v2.z * v2.z + v2.w * v2.w;
        s3 += v3.x + v3.y + v3.z + v3.w; q3 += v3.x * v3.x + v3.y * v3.y + v3.z * v3.z + v3.w * v3.w;
    }
#pragma unroll
    for (int off = 16; off > 0; off >>= 1) {
        s0 += __shfl_down_sync(0xffffffffu, s0, off);
        s1 += __shfl_down_sync(0xffffffffu, s1, off);
        s2 += __shfl_down_sync(0xffffffffu, s2, off);
        s3 += __shfl_down_sync(0xffffffffu, s3, off);
        q0 += __shfl_down_sync(0xffffffffu, q0, off);
        q1 += __shfl_down_sync(0xffffffffu, q1, off);
        q2 += __shfl_down_sync(0xffffffffu, q2, off);
        q3 += __shfl_down_sync(0xffffffffu, q3, off);
    }
    int lane = t & 31, w = t >> 5;
    if (lane == 0) {
        red[w][0] = s0; red[w][1] = s1; red[w][2] = s2; red[w][3] = s3;
        red[w][4] = q0; red[w][5] = q1; red[w][6] = q2; red[w][7] = q3;
    }
    __syncthreads();
    if (t < 8) {
        float a = 0;
        int nw = blockDim.x >> 5;
        for (int k = 0; k < nw; k++) a += red[k][t];
        fin[t] = a;
    }
    __syncthreads();
    if (t < 4) {
        float cnt = (float)(4 * N);
        float mn = fin[t] / cnt;
        float vv = fin[t + 4] / cnt - mn * mn;
        smean[t] = mn;
        sinv[t] = rsqrtf(vv + 1e-5f);
    }
    __syncthreads();
    for (int idx = t; idx < N * 16; idx += blockDim.x) {
        int c = idx & 15;
        int gg = c >> 2;
        xout[idx] = (xin[idx] - smean[gg]) * sinv[gg] * gamma[c] + beta[c];
    }
}
__global__ void kGN_in(const float* __restrict__ gamma, const float* __restrict__ beta, int N) {
    gn_body(g_h1, gamma, beta, g_h, N);
}
__global__ void kGN_out(const float* __restrict__ gamma, const float* __restrict__ beta, int N) {
    gn_body(g_y2, gamma, beta, g_yn, N);
}

// ---------------- Kernel C: load_mesh N^2 ----------------
__global__ void kMesh(const float* __restrict__ nrm, int N) {
    __shared__ float sred[8][16][2];
    int t = threadIdx.x;
    int il = t & 15, slice = t >> 4;
    int i = blockIdx.x * 16 + il;
    if (i >= N) return;

    float pix = g_pm[i * 3 + 0], piy = g_pm[i * 3 + 1], piz = g_pm[i * 3 + 2];
    float nix = nrm[i * 3 + 0], niy = nrm[i * 3 + 1], niz = nrm[i * 3 + 2];
    float ux = g_uv[i * 6 + 0], uy = g_uv[i * 6 + 1], uz = g_uv[i * 6 + 2];
    float vx = g_uv[i * 6 + 3], vy = g_uv[i * 6 + 4], vz = g_uv[i * 6 + 5];

    float ov0 = 0.f, ov1 = 0.f;
    int per = N >> 3;
    int j0 = slice * per;
    for (int j = j0; j < j0 + per; j++) {
        float dx = g_pm[j * 3 + 0] - pix;
        float dy = g_pm[j * 3 + 1] - piy;
        float dz = g_pm[j * 3 + 2] - piz;
        float d2 = dx * dx + dy * dy + dz * dz;
        float cs = nrm[j * 3 + 0] * nix + nrm[j * 3 + 1] * niy + nrm[j * 3 + 2] * niz;
        float tt = 2.f - cs;
        float wj = __expf(-d2 * tt * tt) * g_scores[j];
        ov0 = fmaf(wj, ux * dx + uy * dy + uz * dz, ov0);
        ov1 = fmaf(wj, vx * dx + vy * dy + vz * dz, ov1);
    }
    sred[slice][il][0] = ov0;
    sred[slice][il][1] = ov1;
    __syncthreads();
    if (slice == 0) {
#pragma unroll
        for (int k = 1; k < 8; k++) { ov0 += sred[k][il][0]; ov1 += sred[k][il][1]; }
        ov0 += 1e-5f; ov1 += 1e-5f;
        float nr = fmaxf(sqrtf(ov0 * ov0 + ov1 * ov1), 1e-12f);
        float ex = ov0 / nr, ey = ov1 / nr;
        g_nuv[i * 9 + 0] = nix; g_nuv[i * 9 + 1] = niy; g_nuv[i * 9 + 2] = niz;
        g_nuv[i * 9 + 3] = ex * ux + ey * vx;
        g_nuv[i * 9 + 4] = ex * uy + ey * vy;
        g_nuv[i * 9 + 5] = ex * uz + ey * vz;
        g_nuv[i * 9 + 6] = -ey * ux + ex * vx;
        g_nuv[i * 9 + 7] = -ey * uy + ex * vy;
        g_nuv[i * 9 + 8] = -ey * uz + ex * vz;
    }
}

// ---------------- Kernel D: main conv N^2 (packed, h-split, 3 CTAs/SM) ----------------
#define TI 4
#define TJ 32

// one hp chain: m = relu(B + sum_c A*g); s2 += m * h2
#define DO_HP2(p, h2v) do {                                     \
    unsigned long long m = B2[p];                               \
    m = ffma2(A2[p][0], gA.x, m);                               \
    m = ffma2(A2[p][1], gA.y, m);                               \
    m = ffma2(A2[p][2], gB.x, m);                               \
    m = ffma2(A2[p][3], gB.y, m);                               \
    m = ffma2(A2[p][4], gC.x, m);                               \
    m = ffma2(A2[p][5], gC.y, m);                               \
    m = ffma2(A2[p][6], gD.x, m);                               \
    m = ffma2(A2[p][7], gD.y, m);                               \
    s2 = ffma2(relu2(m), (h2v), s2);                            \
} while (0)

__global__ void __launch_bounds__(128, 3)
kConv(const float* __restrict__ nrm, const float* __restrict__ cva1,
      const float* __restrict__ cvb1, const float* __restrict__ cva2,
      const float* __restrict__ cvb2, int N) {
    // sm_g[ii][c2][jj]: (x = g_{2c2} duplicated, y = g_{2c2+1} duplicated)
    __shared__ __align__(16) ulonglong2 sm_g[TI][4][TJ];
    __shared__ __align__(16) float sm_h[TJ][16];
    __shared__ unsigned long long sm_w[TI][TJ];  // (w, w)
    __shared__ float sm_pi[TI][3];
    __shared__ float sm_nv[TI][9];
    __shared__ float sm_a1[24];
    __shared__ float sm_b1[8];

    int t = threadIdx.x;
    int lane = t & 31, ii = t >> 5;       // warp == one i
    int o = lane & 15, hh = lane >> 4;    // hh in {0,1}: this thread's 8 h's
    int ibase = blockIdx.x * TI;

    // per-thread packed weights: rows o*16 + hh*8 + {0..7} of cv_a2[256][8]
    unsigned long long A2[4][8], B2[4];
#pragma unroll
    for (int p = 0; p < 4; p++) {
        int r0 = (o * 16 + hh * 8 + 2 * p) * 8;
#pragma unroll
        for (int c = 0; c < 8; c++) A2[p][c] = pk2(cva2[r0 + c], cva2[r0 + 8 + c]);
        B2[p] = pk2(cvb2[o * 16 + hh * 8 + 2 * p], cvb2[o * 16 + hh * 8 + 2 * p + 1]);
    }
    if (t < TI) {
        int i = ibase + t;
        sm_pi[t][0] = g_pc[i * 3 + 0];
        sm_pi[t][1] = g_pc[i * 3 + 1];
        sm_pi[t][2] = g_pc[i * 3 + 2];
#pragma unroll
        for (int k = 0; k < 9; k++) sm_nv[t][k] = g_nuv[i * 9 + k];
    }
    if (t >= 32 && t < 56) sm_a1[t - 32] = cva1[t - 32];
    if (t >= 64 && t < 72) sm_b1[t - 64] = cvb1[t - 64];
    __syncthreads();

    unsigned long long acc2 = pk2(0.f, 0.f);
    for (int jt = 0; jt < N; jt += TJ) {
        // ---- phase 1: one (ii, jj) pair per thread ----
        {
            int pjj = lane;
            int j = jt + pjj;
            float pjx = g_pc[j * 3 + 0], pjy = g_pc[j * 3 + 1], pjz = g_pc[j * 3 + 2];
            float njx = nrm[j * 3 + 0], njy = nrm[j * 3 + 1], njz = nrm[j * 3 + 2];
            float dx = pjx - sm_pi[ii][0];
            float dy = pjy - sm_pi[ii][1];
            float dz = pjz - sm_pi[ii][2];
            float d2 = dx * dx + dy * dy + dz * dz;
            float cs = njx * sm_nv[ii][0] + njy * sm_nv[ii][1] + njz * sm_nv[ii][2];
            float tt = 2.f - cs;
            float w = __expf(-d2 * tt * tt);
            float X0 = dx * sm_nv[ii][0] + dy * sm_nv[ii][1] + dz * sm_nv[ii][2];
            float X1 = dx * sm_nv[ii][3] + dy * sm_nv[ii][4] + dz * sm_nv[ii][5];
            float X2 = dx * sm_nv[ii][6] + dy * sm_nv[ii][7] + dz * sm_nv[ii][8];
            sm_w[ii][pjj] = pk2(w, w);
            float gv[8];
#pragma unroll
            for (int c = 0; c < 8; c++) {
                float g = fmaf(X0, sm_a1[c * 3 + 0],
                          fmaf(X1, sm_a1[c * 3 + 1],
                          fmaf(X2, sm_a1[c * 3 + 2], sm_b1[c])));
                gv[c] = fmaxf(g, 0.f);
            }
#pragma unroll
            for (int c2 = 0; c2 < 4; c2++) {
                ulonglong2 v;
                v.x = pk2(gv[2 * c2], gv[2 * c2]);
                v.y = pk2(gv[2 * c2 + 1], gv[2 * c2 + 1]);
                sm_g[ii][c2][pjj] = v;
            }
        }
        // ---- h tile: 128 threads x float4 = 32 rows x 16 floats ----
        reinterpret_cast<float4*>(&sm_h[0][0])[t] =
            reinterpret_cast<const float4*>(g_h + jt * 16)[t];
        __syncthreads();

        // ---- phase 2: packed inner product over this warp's ii ----
        const ulonglong2* gb = &sm_g[ii][0][0];
        const unsigned long long* wb = &sm_w[ii][0];
#pragma unroll 4
        for (int jj = 0; jj < TJ; jj++) {
            ulonglong2 gA = gb[0 * TJ + jj];
            ulonglong2 gB = gb[1 * TJ + jj];
            ulonglong2 gC = gb[2 * TJ + jj];
            ulonglong2 gD = gb[3 * TJ + jj];
            ulonglong2 h01 = *reinterpret_cast<const ulonglong2*>(&sm_h[jj][hh * 8]);
            ulonglong2 h23 = *reinterpret_cast<const ulonglong2*>(&sm_h[jj][hh * 8 + 4]);
            unsigned long long w2 = wb[jj];
            unsigned long long s2 = 0ull;  // (+0.0f, +0.0f)
            DO_HP2(0, h01.x);
            DO_HP2(1, h01.y);
            DO_HP2(2, h23.x);
            DO_HP2(3, h23.y);
            acc2 = ffma2(w2, s2, acc2);
        }
        __syncthreads();
    }
    float2 av = unpk(acc2);
    float v = av.x + av.y;
    v += __shfl_xor_sync(0xffffffffu, v, 16);
    if (hh == 0) g_y[(ibase + ii) * 16 + o] = v;
}

// ---------------- Kernel E1: y -> y2 (no_w MLP with leaky) ----------------
__global__ void kE1(const float* __restrict__ w1, const float* __restrict__ b1,
                    const float* __restrict__ w2, const float* __restrict__ b2, int N) {
    __shared__ float s1[256], s2[256], sb1[16], sb2[16];
    int t = threadIdx.x;
    if (t < 256) { s1[t] = w1[t]; s2[t] = w2[t]; }
    if (t < 16)  { sb1[t] = b1[t]; sb2[t] = b2[t]; }
    __syncthreads();
    int i = blockIdx.x * 256 + t;
    if (i >= N) return;
    float yv[16], t1[16];
#pragma unroll
    for (int k = 0; k < 16; k++) yv[k] = g_y[i * 16 + k];
#pragma unroll
    for (int u = 0; u < 16; u++) {
        float a = sb1[u];
#pragma unroll
        for (int k = 0; k < 16; k++) a = fmaf(yv[k], s1[u * 16 + k], a);
        t1[u] = lk(a);
    }
#pragma unroll
    for (int v = 0; v < 16; v++) {
        float a = sb2[v];
#pragma unroll
        for (int k = 0; k < 16; k++) a = fmaf(t1[k], s2[v * 16 + k], a);
        g_y2[i * 16 + v] = lk(a);
    }
}

// ---------------- Kernel E3: final heads + skip ----------------
__global__ void kE3(const float* __restrict__ feats,
                    const float* __restrict__ llw1, const float* __restrict__ llb1,
                    const float* __restrict__ llw2, const float* __restrict__ llb2,
                    const float* __restrict__ ltw, const float* __restrict__ ltb,
                    float* __restrict__ out, int N) {
    __shared__ float sW1[256], sW2[256], sWt[256], sB1[16], sB2[16], sBt[16];
    int t = threadIdx.x;
    if (t < 256) { sW1[t] = llw1[t]; sW2[t] = llw2[t]; sWt[t] = ltw[t]; }
    if (t < 16)  { sB1[t] = llb1[t]; sB2[t] = llb2[t]; sBt[t] = ltb[t]; }
    __syncthreads();
    int i = blockIdx.x * 256 + t;
    if (i >= N) return;
    float yn[16], f[16], t1[16];
#pragma unroll
    for (int k = 0; k < 16; k++) yn[k] = g_yn[i * 16 + k];
#pragma unroll
    for (int k = 0; k < 16; k++) f[k] = feats[i * 16 + k];
#pragma unroll
    for (int u = 0; u < 16; u++) {
        float a = sB1[u];
#pragma unroll
        for (int k = 0; k < 16; k++) a = fmaf(yn[k], sW1[u * 16 + k], a);
        t1[u] = fmaxf(a, 0.f);
    }
#pragma unroll
    for (int v = 0; v < 16; v++) {
        float xi = sB2[v];
#pragma unroll
        for (int k = 0; k < 16; k++) xi = fmaf(t1[k], sW2[v * 16 + k], xi);
        float xl = sBt[v];
#pragma unroll
        for (int k = 0; k < 16; k++) xl = fmaf(f[k], sWt[v * 16 + k], xl);
        out[i * 16 + v] = xl + xi;
    }
}

// ---------------- launch ----------------
extern "C" void kernel_launch(void* const* d_in, const int* in_sizes, int n_in,
                              void* d_out, int out_size) {
    const float* xyz    = (const float*)d_in[0];
    const float* nrm    = (const float*)d_in[1];
    const float* feats  = (const float*)d_in[2];
    const float* osw1   = (const float*)d_in[3];
    const float* osb1   = (const float*)d_in[4];
    const float* osw2   = (const float*)d_in[5];
    const float* osb2   = (const float*)d_in[6];
    const float* niw1   = (const float*)d_in[7];
    const float* nib1   = (const float*)d_in[8];
    const float* niw2   = (const float*)d_in[9];
    const float* nib2   = (const float*)d_in[10];
    const float* gnig   = (const float*)d_in[11];
    const float* gnib   = (const float*)d_in[12];
    const float* cva1   = (const float*)d_in[13];
    const float* cvb1   = (const float*)d_in[14];
    const float* cva2   = (const float*)d_in[15];
    const float* cvb2   = (const float*)d_in[16];
    const float* now1   = (const float*)d_in[17];
    const float* nob1   = (const float*)d_in[18];
    const float* now2   = (const float*)d_in[19];
    const float* nob2   = (const float*)d_in[20];
    const float* gnog   = (const float*)d_in[21];
    const float* gnob   = (const float*)d_in[22];
    const float* llw1   = (const float*)d_in[23];
    const float* llb1   = (const float*)d_in[24];
    const float* llw2   = (const float*)d_in[25];
    const float* llb2   = (const float*)d_in[26];
    const float* ltw    = (const float*)d_in[27];
    const float* ltb    = (const float*)d_in[28];
    float* out = (float*)d_out;

    int N = in_sizes[0] / 3;  // 4096

    kA<<<(N + 255) / 256, 256>>>(xyz, nrm, feats, osw1, osb1, osw2, osb2,
                                 niw1, nib1, niw2, nib2, N);
    kGN_in<<<1, 1024>>>(gnig, gnib, N);
    kMesh<<<N / 16, 128>>>(nrm, N);
    kConv<<<N / TI, 128>>>(nrm, cva1, cvb1, cva2, cvb2, N);
    kE1<<<(N + 255) / 256, 256>>>(now1, nob1, now2, nob2, N);
    kGN_out<<<1, 1024>>>(gnog, gnob, N);
    kE3<<<(N + 255) / 256, 256>>>(feats, llw1, llb1, llw2, llb2, ltw, ltb, out, N);
}